// round 5
// baseline (speedup 1.0000x reference)
#include <cuda_runtime.h>
#include <cuda_fp16.h>

#define N_NODES 100000
#define N_EDGES 1600000
#define D 48
#define D4 (D / 4)
#define SCAN_TILE 1024
#define N_TILES ((N_NODES + SCAN_TILE - 1) / SCAN_TILE)   // 98

#define GEMM_T 256
#define GEMM_NODES_PER_BLK (2 * GEMM_T)                    // 512
#define GEMM_BLOCKS ((N_NODES + GEMM_NODES_PER_BLK - 1) / GEMM_NODES_PER_BLK) // 196
#define HIST_BLOCKS ((N_EDGES + 255) / 256)                // 6250

// Device scratch (no allocations allowed):
__device__ __half g_xw[N_NODES * D];        // x @ w in fp16 (9.6 MB)
__device__ int    g_cnt[N_NODES];           // histogram -> cursor
__device__ int    g_off[N_NODES + 1];       // CSR row offsets
__device__ unsigned long long g_tile[N_TILES];  // lookback status words
__device__ uint2  g_rec[N_EDGES];           // (src, val) sorted by dst (12.8 MB)

// ---------------------------------------------------------------------------
// 1) zero histogram counters + tile status
// ---------------------------------------------------------------------------
__global__ void init_kernel() {
    int i = blockIdx.x * blockDim.x + threadIdx.x;
    if (i < N_NODES) g_cnt[i] = 0;
    if (i < N_TILES) g_tile[i] = 0ULL;
}

// ---------------------------------------------------------------------------
// 2) fused kernel: blocks [0, GEMM_BLOCKS) do the dense GEMM (FMA-bound),
//    blocks [GEMM_BLOCKS, ...) do the dst histogram (atomic/L2-bound).
//    They are independent; co-residency overlaps the two pipes.
// ---------------------------------------------------------------------------
__global__ void __launch_bounds__(256, 2)
gemm_hist_kernel(const float* __restrict__ x, const float* __restrict__ w,
                 const int* __restrict__ dst) {
    if (blockIdx.x >= GEMM_BLOCKS) {
        // ---- histogram path ----
        int e = (blockIdx.x - GEMM_BLOCKS) * blockDim.x + threadIdx.x;
        if (e < N_EDGES) atomicAdd(&g_cnt[__ldg(dst + e)], 1);
        return;
    }
    // ---- GEMM path: two nodes per thread ----
    __shared__ float ws[D * D];
    for (int i = threadIdx.x; i < D * D; i += blockDim.x) ws[i] = w[i];
    __syncthreads();

    int base = blockIdx.x * GEMM_NODES_PER_BLK + threadIdx.x;
    int n0 = base;
    int n1 = base + blockDim.x;
    bool has0 = (n0 < N_NODES);
    bool has1 = (n1 < N_NODES);
    if (!has0) return;

    float4 xa[D4], xb[D4];
    const float4* xp0 = (const float4*)(x + (size_t)n0 * D);
    const float4* xp1 = (const float4*)(x + (size_t)n1 * D);
#pragma unroll
    for (int k4 = 0; k4 < D4; k4++) {
        xa[k4] = xp0[k4];
        xb[k4] = has1 ? xp1[k4] : make_float4(0.f, 0.f, 0.f, 0.f);
    }

    __half* hp0 = g_xw + (size_t)n0 * D;
    __half* hp1 = g_xw + (size_t)n1 * D;

#pragma unroll
    for (int j4 = 0; j4 < D4; j4++) {
        float a0 = 0.f, a1 = 0.f, a2 = 0.f, a3 = 0.f;
        float b0 = 0.f, b1 = 0.f, b2 = 0.f, b3 = 0.f;
#pragma unroll
        for (int k4 = 0; k4 < D4; k4++) {
            float4 va = xa[k4];
            float4 vb = xb[k4];
#pragma unroll
            for (int t = 0; t < 4; t++) {
                int k = k4 * 4 + t;
                float xav = (t == 0) ? va.x : (t == 1) ? va.y : (t == 2) ? va.z : va.w;
                float xbv = (t == 0) ? vb.x : (t == 1) ? vb.y : (t == 2) ? vb.z : vb.w;
                float4 wr = *(const float4*)(ws + k * D + j4 * 4);
                a0 = fmaf(xav, wr.x, a0);
                a1 = fmaf(xav, wr.y, a1);
                a2 = fmaf(xav, wr.z, a2);
                a3 = fmaf(xav, wr.w, a3);
                b0 = fmaf(xbv, wr.x, b0);
                b1 = fmaf(xbv, wr.y, b1);
                b2 = fmaf(xbv, wr.z, b2);
                b3 = fmaf(xbv, wr.w, b3);
            }
        }
        __half2 ha[2], hb[2];
        ha[0] = __floats2half2_rn(a0, a1);
        ha[1] = __floats2half2_rn(a2, a3);
        hb[0] = __floats2half2_rn(b0, b1);
        hb[1] = __floats2half2_rn(b2, b3);
        *(uint2*)(hp0 + j4 * 4) = *(const uint2*)ha;
        if (has1) *(uint2*)(hp1 + j4 * 4) = *(const uint2*)hb;
    }
}

// ---------------------------------------------------------------------------
// 3) single-pass decoupled-lookback exclusive scan of g_cnt -> g_off;
//    also initializes the build cursors (g_cnt = offset).
//    98 blocks — all co-resident in one wave, so lookback cannot deadlock.
//    Status word: (value << 2) | status; status: 1=aggregate, 2=inclusive prefix.
// ---------------------------------------------------------------------------
__global__ void scan_kernel() {
    __shared__ int ssum[256];
    __shared__ int sh_excl;
    int b = blockIdx.x;
    int t = threadIdx.x;
    int lane = t & 31;
    int base = b * SCAN_TILE + t * 4;

    int4 c = make_int4(0, 0, 0, 0);
    if (base + 3 < N_NODES) c = *(const int4*)(g_cnt + base);   // N_NODES % 4 == 0
    int tsum = c.x + c.y + c.z + c.w;

    // block-wide inclusive scan of tsum
    ssum[t] = tsum;
    __syncthreads();
    for (int off = 1; off < 256; off <<= 1) {
        int u = (t >= off) ? ssum[t - off] : 0;
        __syncthreads();
        ssum[t] += u;
        __syncthreads();
    }
    int total = ssum[255];

    // publish aggregate (or final prefix for tile 0) ASAP
    if (t == 0) {
        unsigned long long pub = ((unsigned long long)total << 2) |
                                 (b == 0 ? 2ULL : 1ULL);
        atomicExch(&g_tile[b], pub);
        if (b == 0) sh_excl = 0;
    }

    // warp 0: parallel lookback
    if (b > 0 && t < 32) {
        int excl = 0;
        int j = b - 1;
        bool done = false;
        while (!done) {
            int idx = j - lane;
            unsigned long long wv;
            int st;
            while (true) {
                wv = (idx >= 0) ? *((volatile unsigned long long*)&g_tile[idx])
                                : 2ULL;   // virtual tile: prefix 0
                st = (int)(wv & 3ULL);
                if (__all_sync(0xffffffffu, st != 0)) break;
            }
            int val = (int)(wv >> 2);
            unsigned pm = __ballot_sync(0xffffffffu, st == 2);
            int px = __ffs(pm) - 1;     // nearest predecessor with full prefix
            int contrib;
            if (px < 0) {
                contrib = val;          // all aggregates, keep walking
            } else {
                contrib = (lane <= px) ? val : 0;
                done = true;
            }
#pragma unroll
            for (int o = 16; o; o >>= 1)
                contrib += __shfl_down_sync(0xffffffffu, contrib, o);
            excl += __shfl_sync(0xffffffffu, contrib, 0);
            j -= 32;
        }
        if (lane == 0) {
            sh_excl = excl;
            atomicExch(&g_tile[b],
                       ((unsigned long long)(excl + total) << 2) | 2ULL);
        }
    }
    __syncthreads();

    int row0 = sh_excl + ssum[t] - tsum;
    int p1 = row0 + c.x;
    int p2 = p1 + c.y;
    int p3 = p2 + c.z;
    if (base < N_NODES) {
        g_off[base + 0] = row0;  g_cnt[base + 0] = row0;
        g_off[base + 1] = p1;    g_cnt[base + 1] = p1;
        g_off[base + 2] = p2;    g_cnt[base + 2] = p2;
        g_off[base + 3] = p3;    g_cnt[base + 3] = p3;
    }
    if (b == 0 && t == 0) g_off[N_NODES] = N_EDGES;
}

// ---------------------------------------------------------------------------
// 4) scatter edges into dst-sorted record array
// ---------------------------------------------------------------------------
__global__ void build_kernel(const int* __restrict__ src,
                             const int* __restrict__ dst,
                             const float* __restrict__ vals) {
    int e = blockIdx.x * blockDim.x + threadIdx.x;
    if (e >= N_EDGES) return;
    int d = __ldg(dst + e);
    int pos = atomicAdd(&g_cnt[d], 1);
    g_rec[pos] = make_uint2((unsigned)__ldg(src + e),
                            __float_as_uint(__ldg(vals + e)));
}

// ---------------------------------------------------------------------------
// 5) one warp per dst node: gather xw[src], accumulate, write relu(agg+b).
//    Lanes 0..23 own 2 columns each. Unroll 4 for MLP on the gather chain.
// ---------------------------------------------------------------------------
__global__ void reduce_kernel(const float* __restrict__ b,
                              float* __restrict__ out) {
    int gwid = (blockIdx.x * blockDim.x + threadIdx.x) >> 5;
    int lane = threadIdx.x & 31;
    if (gwid >= N_NODES) return;

    int start = g_off[gwid];
    int end   = g_off[gwid + 1];

    float accx = 0.f, accy = 0.f;
    int i = start;
    for (; i + 3 < end; i += 4) {
        uint2 r0 = g_rec[i];
        uint2 r1 = g_rec[i + 1];
        uint2 r2 = g_rec[i + 2];
        uint2 r3 = g_rec[i + 3];
        if (lane < 24) {
            __half2 h0 = *((const __half2*)(g_xw + (size_t)r0.x * D) + lane);
            __half2 h1 = *((const __half2*)(g_xw + (size_t)r1.x * D) + lane);
            __half2 h2 = *((const __half2*)(g_xw + (size_t)r2.x * D) + lane);
            __half2 h3 = *((const __half2*)(g_xw + (size_t)r3.x * D) + lane);
            float2 f0 = __half22float2(h0);
            float2 f1 = __half22float2(h1);
            float2 f2 = __half22float2(h2);
            float2 f3 = __half22float2(h3);
            float a0 = __uint_as_float(r0.y);
            float a1 = __uint_as_float(r1.y);
            float a2 = __uint_as_float(r2.y);
            float a3 = __uint_as_float(r3.y);
            accx = fmaf(a0, f0.x, accx);  accy = fmaf(a0, f0.y, accy);
            accx = fmaf(a1, f1.x, accx);  accy = fmaf(a1, f1.y, accy);
            accx = fmaf(a2, f2.x, accx);  accy = fmaf(a2, f2.y, accy);
            accx = fmaf(a3, f3.x, accx);  accy = fmaf(a3, f3.y, accy);
        }
    }
    for (; i < end; i++) {
        uint2 r0 = g_rec[i];
        if (lane < 24) {
            __half2 h0 = *((const __half2*)(g_xw + (size_t)r0.x * D) + lane);
            float2 f0 = __half22float2(h0);
            float a0 = __uint_as_float(r0.y);
            accx = fmaf(a0, f0.x, accx);  accy = fmaf(a0, f0.y, accy);
        }
    }

    if (lane < 24) {
        float2 bb = *(const float2*)(b + 2 * lane);
        float2 o;
        o.x = fmaxf(accx + bb.x, 0.f);
        o.y = fmaxf(accy + bb.y, 0.f);
        *(float2*)(out + (size_t)gwid * D + 2 * lane) = o;
    }
}

// ---------------------------------------------------------------------------
extern "C" void kernel_launch(void* const* d_in, const int* in_sizes, int n_in,
                              void* d_out, int out_size) {
    const float* x        = (const float*)d_in[0];
    const float* w        = (const float*)d_in[1];
    const float* b        = (const float*)d_in[2];
    const int*   edge_src = (const int*)d_in[3];
    const int*   edge_dst = (const int*)d_in[4];
    const float* adj_vals = (const float*)d_in[5];
    float* out = (float*)d_out;

    const int T = 256;

    init_kernel<<<(N_NODES + T - 1) / T, T>>>();
    gemm_hist_kernel<<<GEMM_BLOCKS + HIST_BLOCKS, T>>>(x, w, edge_dst);
    scan_kernel<<<N_TILES, 256>>>();
    build_kernel<<<HIST_BLOCKS, T>>>(edge_src, edge_dst, adj_vals);
    reduce_kernel<<<(N_NODES * 32 + T - 1) / T, T>>>(b, out);
}

// round 6
// speedup vs baseline: 1.8129x; 1.8129x over previous
#include <cuda_runtime.h>
#include <cuda_fp16.h>

#define N_NODES 100000
#define N_EDGES 1600000
#define D 48
#define D4 (D / 4)

#define T 256
#define GEMM_NODES_PER_BLK (2 * T)                                   // 512
#define GEMM_BLOCKS ((N_NODES + GEMM_NODES_PER_BLK - 1) / GEMM_NODES_PER_BLK) // 196
#define AGG_U4 (N_NODES * D / 8)                                     // 600000 uint4 chunks
#define ZERO_BLOCKS ((AGG_U4 + T - 1) / T)                           // 2344

// Device scratch (no allocations allowed):
__device__ __half g_xw[N_NODES * D];    // x @ w in fp16 (9.6 MB)
__device__ __half g_agg[N_NODES * D];   // fp16 accumulator (9.6 MB)

// ---------------------------------------------------------------------------
// Kernel 1 (fused): blocks [0, GEMM_BLOCKS) compute g_xw = x @ w (FMA-bound);
// blocks [GEMM_BLOCKS, +ZERO_BLOCKS) zero g_agg (store-bound). Independent.
// ---------------------------------------------------------------------------
__global__ void __launch_bounds__(256, 2)
gemm_zero_kernel(const float* __restrict__ x, const float* __restrict__ w) {
    if (blockIdx.x >= GEMM_BLOCKS) {
        int i = (blockIdx.x - GEMM_BLOCKS) * blockDim.x + threadIdx.x;
        if (i < AGG_U4)
            ((uint4*)g_agg)[i] = make_uint4(0u, 0u, 0u, 0u);
        return;
    }

    __shared__ float ws[D * D];
    for (int i = threadIdx.x; i < D * D; i += blockDim.x) ws[i] = w[i];
    __syncthreads();

    int base = blockIdx.x * GEMM_NODES_PER_BLK + threadIdx.x;
    int n0 = base;
    int n1 = base + blockDim.x;
    bool has0 = (n0 < N_NODES);
    bool has1 = (n1 < N_NODES);
    if (!has0) return;

    float4 xa[D4], xb[D4];
    const float4* xp0 = (const float4*)(x + (size_t)n0 * D);
    const float4* xp1 = (const float4*)(x + (size_t)n1 * D);
#pragma unroll
    for (int k4 = 0; k4 < D4; k4++) {
        xa[k4] = xp0[k4];
        xb[k4] = has1 ? xp1[k4] : make_float4(0.f, 0.f, 0.f, 0.f);
    }

    __half* hp0 = g_xw + (size_t)n0 * D;
    __half* hp1 = g_xw + (size_t)n1 * D;

#pragma unroll
    for (int j4 = 0; j4 < D4; j4++) {
        float a0 = 0.f, a1 = 0.f, a2 = 0.f, a3 = 0.f;
        float b0 = 0.f, b1 = 0.f, b2 = 0.f, b3 = 0.f;
#pragma unroll
        for (int k4 = 0; k4 < D4; k4++) {
            float4 va = xa[k4];
            float4 vb = xb[k4];
#pragma unroll
            for (int t = 0; t < 4; t++) {
                int k = k4 * 4 + t;
                float xav = (t == 0) ? va.x : (t == 1) ? va.y : (t == 2) ? va.z : va.w;
                float xbv = (t == 0) ? vb.x : (t == 1) ? vb.y : (t == 2) ? vb.z : vb.w;
                float4 wr = *(const float4*)(ws + k * D + j4 * 4);
                a0 = fmaf(xav, wr.x, a0);
                a1 = fmaf(xav, wr.y, a1);
                a2 = fmaf(xav, wr.z, a2);
                a3 = fmaf(xav, wr.w, a3);
                b0 = fmaf(xbv, wr.x, b0);
                b1 = fmaf(xbv, wr.y, b1);
                b2 = fmaf(xbv, wr.z, b2);
                b3 = fmaf(xbv, wr.w, b3);
            }
        }
        __half2 ha[2], hb[2];
        ha[0] = __floats2half2_rn(a0, a1);
        ha[1] = __floats2half2_rn(a2, a3);
        hb[0] = __floats2half2_rn(b0, b1);
        hb[1] = __floats2half2_rn(b2, b3);
        *(uint2*)(hp0 + j4 * 4) = *(const uint2*)ha;
        if (has1) *(uint2*)(hp1 + j4 * 4) = *(const uint2*)hb;
    }
}

// ---------------------------------------------------------------------------
// Kernel 2: COO scatter, fp16 all the way.
// 6 lanes per edge; lane c gathers 16 B (8 halves) of xw[src], scales by
// adj_val (fp32 math, fp16 round), and issues ONE red.v4.f16x2 (16 B).
// Adjacent lanes cover a contiguous 96 B row -> 3 L2 sectors per edge.
// ---------------------------------------------------------------------------
__global__ void scatter_kernel(const int* __restrict__ src,
                               const int* __restrict__ dst,
                               const float* __restrict__ vals) {
    int tid = blockIdx.x * blockDim.x + threadIdx.x;
    if (tid >= N_EDGES * 6) return;
    int e = tid / 6;
    int c = tid - e * 6;

    int s = __ldg(src + e);
    int d = __ldg(dst + e);
    float a = __ldg(vals + e);

    float4 raw = *(const float4*)(g_xw + (size_t)s * D + c * 8);
    const __half2* h = (const __half2*)&raw;
    unsigned r[4];
#pragma unroll
    for (int t = 0; t < 4; t++) {
        float2 f = __half22float2(h[t]);
        __half2 o = __floats2half2_rn(a * f.x, a * f.y);
        r[t] = *(const unsigned*)&o;
    }

    __half* p = g_agg + (size_t)d * D + c * 8;
    asm volatile("red.global.add.noftz.v4.f16x2 [%0], {%1, %2, %3, %4};"
                 :: "l"(p), "r"(r[0]), "r"(r[1]), "r"(r[2]), "r"(r[3])
                 : "memory");
}

// ---------------------------------------------------------------------------
// Kernel 3: out = relu(agg + b). Each thread: 8 halves in, 8 floats out.
// ---------------------------------------------------------------------------
__global__ void finalize_kernel(const float* __restrict__ b,
                                float* __restrict__ out) {
    int i = blockIdx.x * blockDim.x + threadIdx.x;
    if (i >= AGG_U4) return;
    int c = i % 6;                      // which 8-column chunk within the row

    uint4 raw = *((const uint4*)g_agg + i);
    const __half2* h = (const __half2*)&raw;

    float bb[8];
    *(float4*)(bb)     = *(const float4*)(b + c * 8);
    *(float4*)(bb + 4) = *(const float4*)(b + c * 8 + 4);

    float4 o0, o1;
    float2 f0 = __half22float2(h[0]);
    float2 f1 = __half22float2(h[1]);
    float2 f2 = __half22float2(h[2]);
    float2 f3 = __half22float2(h[3]);
    o0.x = fmaxf(f0.x + bb[0], 0.f);
    o0.y = fmaxf(f0.y + bb[1], 0.f);
    o0.z = fmaxf(f1.x + bb[2], 0.f);
    o0.w = fmaxf(f1.y + bb[3], 0.f);
    o1.x = fmaxf(f2.x + bb[4], 0.f);
    o1.y = fmaxf(f2.y + bb[5], 0.f);
    o1.z = fmaxf(f3.x + bb[6], 0.f);
    o1.w = fmaxf(f3.y + bb[7], 0.f);

    float4* op = (float4*)(out + (size_t)i * 8);
    op[0] = o0;
    op[1] = o1;
}

// ---------------------------------------------------------------------------
extern "C" void kernel_launch(void* const* d_in, const int* in_sizes, int n_in,
                              void* d_out, int out_size) {
    const float* x        = (const float*)d_in[0];
    const float* w        = (const float*)d_in[1];
    const float* b        = (const float*)d_in[2];
    const int*   edge_src = (const int*)d_in[3];
    const int*   edge_dst = (const int*)d_in[4];
    const float* adj_vals = (const float*)d_in[5];
    float* out = (float*)d_out;

    // 1) fused GEMM + zero(g_agg)
    gemm_zero_kernel<<<GEMM_BLOCKS + ZERO_BLOCKS, T>>>(x, w);
    // 2) scatter-add over edges (fp16 gather, fp16x2 vector RED)
    {
        int total = N_EDGES * 6;
        scatter_kernel<<<(total + T - 1) / T, T>>>(edge_src, edge_dst, adj_vals);
    }
    // 3) out = relu(agg + b)
    finalize_kernel<<<(AGG_U4 + T - 1) / T, T>>>(b, out);
}